// round 1
// baseline (speedup 1.0000x reference)
#include <cuda_runtime.h>
#include <cuda_bf16.h>
#include <math.h>

// ---------------------------------------------------------------------------
// MLA forward, fp32 SIMT baseline.
//   Q = X Wq^T ; K = X Wk^T ; V = X Wv^T
//   RoPE on pe slices of Q,K
//   S_h = causal( (Q_h K_h^T) * 192^-0.5 ) ; P = softmax(S)
//   O_h = P_h V_h ;  Y = O Wo^T
// ---------------------------------------------------------------------------

#define SEQ   2048
#define DIM   2048
#define NH    16
#define HD    192          // 128 nope + 64 rope
#define NOPE  128
#define ROPE  64
#define VD    128
#define QKLD  (NH * HD)    // 3072

// scratch (allocation-free: __device__ globals)
__device__ float g_q[SEQ * QKLD];
__device__ float g_k[SEQ * QKLD];
__device__ float g_v[SEQ * DIM];
__device__ float g_s[(long long)NH * SEQ * SEQ];   // 256 MB scores/probs
__device__ float g_o[SEQ * DIM];

// ---------------------------------------------------------------------------
// 128x128x8 tiled SGEMM, 256 threads, 8x8 per-thread microtile.
//   BT=true :  C = A * B^T   (A[M,K] lda, B[N,K] ldb)
//   BT=false:  C = A * B     (A[M,K] lda, B[K,N] ldb)
// CSKIP: skip blocks strictly above the diagonal (causal scores)
// KLIM : limit k-loop to m0+128 (causal PV)
// batched over blockIdx.z with element strides sA/sB/sC.
// ---------------------------------------------------------------------------
template<bool BT, bool CSKIP, bool KLIM>
__global__ __launch_bounds__(256)
void gemm128(const float* __restrict__ A, const float* __restrict__ B,
             float* __restrict__ C,
             int M, int N, int K, int lda, int ldb, int ldc,
             long long sA, long long sB, long long sC)
{
    A += (long long)blockIdx.z * sA;
    B += (long long)blockIdx.z * sB;
    C += (long long)blockIdx.z * sC;

    const int m0 = blockIdx.y * 128;
    const int n0 = blockIdx.x * 128;
    if (CSKIP && n0 > m0) return;
    const int kend = KLIM ? min(K, m0 + 128) : K;

    __shared__ float As[8][132];
    __shared__ float Bs[8][132];

    const int tid = threadIdx.x;
    const int tx  = tid & 15;
    const int ty  = tid >> 4;

    // A tile loader: 128 rows x 8 cols, float4 per thread
    const int arow = tid >> 1;
    const int acol = (tid & 1) << 2;
    const float* Aptr = A + (long long)(m0 + arow) * lda + acol;

    const float* Bptr;
    int brow, bcol;
    if (BT) {
        brow = tid >> 1; bcol = (tid & 1) << 2;
        Bptr = B + (long long)(n0 + brow) * ldb + bcol;
    } else {
        brow = tid >> 5; bcol = (tid & 31) << 2;
        Bptr = B + (long long)brow * ldb + n0 + bcol;
    }

    float acc[8][8];
    #pragma unroll
    for (int i = 0; i < 8; i++)
        #pragma unroll
        for (int j = 0; j < 8; j++) acc[i][j] = 0.f;

    for (int k0 = 0; k0 < kend; k0 += 8) {
        float4 av = *(const float4*)(Aptr + k0);
        As[acol + 0][arow] = av.x;
        As[acol + 1][arow] = av.y;
        As[acol + 2][arow] = av.z;
        As[acol + 3][arow] = av.w;
        if (BT) {
            float4 bv = *(const float4*)(Bptr + k0);
            Bs[bcol + 0][brow] = bv.x;
            Bs[bcol + 1][brow] = bv.y;
            Bs[bcol + 2][brow] = bv.z;
            Bs[bcol + 3][brow] = bv.w;
        } else {
            float4 bv = *(const float4*)(Bptr + (long long)k0 * ldb);
            *(float4*)&Bs[brow][bcol] = bv;
        }
        __syncthreads();

        #pragma unroll
        for (int kk = 0; kk < 8; kk++) {
            float4 a0 = *(const float4*)&As[kk][ty * 4];
            float4 a1 = *(const float4*)&As[kk][64 + ty * 4];
            float4 b0 = *(const float4*)&Bs[kk][tx * 4];
            float4 b1 = *(const float4*)&Bs[kk][64 + tx * 4];
            float a[8] = {a0.x, a0.y, a0.z, a0.w, a1.x, a1.y, a1.z, a1.w};
            float b[8] = {b0.x, b0.y, b0.z, b0.w, b1.x, b1.y, b1.z, b1.w};
            #pragma unroll
            for (int i = 0; i < 8; i++)
                #pragma unroll
                for (int j = 0; j < 8; j++)
                    acc[i][j] += a[i] * b[j];
        }
        __syncthreads();
    }

    #pragma unroll
    for (int i = 0; i < 8; i++) {
        int row = m0 + ((i < 4) ? (ty * 4 + i) : (64 + ty * 4 + (i - 4)));
        float4 c0 = {acc[i][0], acc[i][1], acc[i][2], acc[i][3]};
        float4 c1 = {acc[i][4], acc[i][5], acc[i][6], acc[i][7]};
        *(float4*)(C + (long long)row * ldc + n0 + tx * 4)      = c0;
        *(float4*)(C + (long long)row * ldc + n0 + 64 + tx * 4) = c1;
    }
}

// ---------------------------------------------------------------------------
// RoPE on pe slice of Q and K (interleaved pairs: a=x[2i], b=x[2i+1])
// ---------------------------------------------------------------------------
__global__ void rope_kernel(float* __restrict__ Q, float* __restrict__ K,
                            const float* __restrict__ cosT,
                            const float* __restrict__ sinT)
{
    int idx = blockIdx.x * blockDim.x + threadIdx.x;   // SEQ*NH*32 total
    if (idx >= SEQ * NH * (ROPE / 2)) return;
    int i = idx & 31;
    int h = (idx >> 5) & 15;
    int s = idx >> 9;
    float c  = cosT[s * 32 + i];
    float sn = sinT[s * 32 + i];
    long long base = (long long)s * QKLD + h * HD + NOPE + 2 * i;
    float a, b;
    a = Q[base]; b = Q[base + 1];
    Q[base] = a * c - b * sn;  Q[base + 1] = a * sn + b * c;
    a = K[base]; b = K[base + 1];
    K[base] = a * c - b * sn;  K[base + 1] = a * sn + b * c;
}

// ---------------------------------------------------------------------------
// In-place causal softmax over score rows. grid = (SEQ, NH), 256 threads.
// softmax(scale*x) restricted to t <= s ; zeros written for t > s.
// ---------------------------------------------------------------------------
__global__ void softmax_causal(float* __restrict__ S, float scale)
{
    const int s = blockIdx.x;
    const int h = blockIdx.y;
    float* row = S + ((long long)h * SEQ + s) * SEQ;
    const int n = s + 1;
    const int tid = threadIdx.x;
    __shared__ float red[8];

    // max
    float m = -1e30f;
    for (int t = tid; t < n; t += 256) m = fmaxf(m, row[t]);
    #pragma unroll
    for (int o = 16; o; o >>= 1) m = fmaxf(m, __shfl_xor_sync(0xffffffffu, m, o));
    if ((tid & 31) == 0) red[tid >> 5] = m;
    __syncthreads();
    if (tid < 8) {
        float v = red[tid];
        #pragma unroll
        for (int o = 4; o; o >>= 1) v = fmaxf(v, __shfl_xor_sync(0xffu, v, o));
        if (tid == 0) red[0] = v;
    }
    __syncthreads();
    m = red[0];
    __syncthreads();

    // sum of exp
    float sum = 0.f;
    for (int t = tid; t < n; t += 256) sum += __expf((row[t] - m) * scale);
    #pragma unroll
    for (int o = 16; o; o >>= 1) sum += __shfl_xor_sync(0xffffffffu, sum, o);
    if ((tid & 31) == 0) red[tid >> 5] = sum;
    __syncthreads();
    if (tid < 8) {
        float v = red[tid];
        #pragma unroll
        for (int o = 4; o; o >>= 1) v += __shfl_xor_sync(0xffu, v, o);
        if (tid == 0) red[0] = v;
    }
    __syncthreads();
    const float inv = 1.f / red[0];

    for (int t = tid; t < SEQ; t += 256)
        row[t] = (t < n) ? __expf((row[t] - m) * scale) * inv : 0.f;
}

// ---------------------------------------------------------------------------
extern "C" void kernel_launch(void* const* d_in, const int* in_sizes, int n_in,
                              void* d_out, int out_size)
{
    const float* x   = (const float*)d_in[0];
    const float* wq  = (const float*)d_in[1];
    const float* wk  = (const float*)d_in[2];
    const float* wv  = (const float*)d_in[3];
    const float* wo  = (const float*)d_in[4];
    const float* fc  = (const float*)d_in[5];
    const float* fs  = (const float*)d_in[6];
    // d_in[7] = mask (unused: causal triu(-1e9) applied analytically)
    // d_in[8] = start_pos (0)
    float* out = (float*)d_out;

    static float *q = nullptr, *k = nullptr, *v = nullptr, *sc = nullptr, *o = nullptr;
    if (!q) {
        cudaGetSymbolAddress((void**)&q,  g_q);
        cudaGetSymbolAddress((void**)&k,  g_k);
        cudaGetSymbolAddress((void**)&v,  g_v);
        cudaGetSymbolAddress((void**)&sc, g_s);
        cudaGetSymbolAddress((void**)&o,  g_o);
    }

    // Projections: C = A * W^T
    gemm128<true, false, false><<<dim3(QKLD / 128, SEQ / 128, 1), 256>>>(
        x, wq, q, SEQ, QKLD, DIM, DIM, DIM, QKLD, 0, 0, 0);
    gemm128<true, false, false><<<dim3(QKLD / 128, SEQ / 128, 1), 256>>>(
        x, wk, k, SEQ, QKLD, DIM, DIM, DIM, QKLD, 0, 0, 0);
    gemm128<true, false, false><<<dim3(DIM / 128, SEQ / 128, 1), 256>>>(
        x, wv, v, SEQ, DIM, DIM, DIM, DIM, DIM, 0, 0, 0);

    // RoPE
    {
        int total = SEQ * NH * (ROPE / 2);
        rope_kernel<<<(total + 255) / 256, 256>>>(q, k, fc, fs);
    }

    // Scores: per-head NT GEMM, causal block skip
    gemm128<true, true, false><<<dim3(SEQ / 128, SEQ / 128, NH), 256>>>(
        q, k, sc, SEQ, SEQ, HD, QKLD, QKLD, SEQ,
        HD, HD, (long long)SEQ * SEQ);

    // Softmax (scale = HEAD_DIM^-0.5)
    softmax_causal<<<dim3(SEQ, NH), 256>>>(sc, rsqrtf((float)HD));

    // PV: per-head NN GEMM, causal K-limit
    gemm128<false, false, true><<<dim3(VD / 128, SEQ / 128, NH), 256>>>(
        sc, v, o, SEQ, VD, SEQ, SEQ, DIM, DIM,
        (long long)SEQ * SEQ, VD, VD);

    // Output projection: Y = O * Wo^T
    gemm128<true, false, false><<<dim3(DIM / 128, SEQ / 128, 1), 256>>>(
        o, wo, out, SEQ, DIM, DIM, DIM, DIM, DIM, 0, 0, 0);
}

// round 3
// speedup vs baseline: 2.1554x; 2.1554x over previous
#include <cuda_runtime.h>
#include <cuda_fp16.h>
#include <cstdint>
#include <math.h>

#define SEQ 2048
#define DIM 2048
#define NH 16
#define HD 192
#define NOPE 128
#define ROPE 64
#define VD 128
#define QKLD (NH*HD)   // 3072

// ---------------------------------------------------------------------------
// split-fp16 scratch (allocation-free __device__ globals)
// ---------------------------------------------------------------------------
__device__ __half g_xh [SEQ*DIM],   g_xl [SEQ*DIM];
__device__ __half g_wqh[QKLD*DIM],  g_wql[QKLD*DIM];
__device__ __half g_wkh[QKLD*DIM],  g_wkl[QKLD*DIM];
__device__ __half g_wvh[DIM*DIM],   g_wvl[DIM*DIM];
__device__ __half g_woh[DIM*DIM],   g_wol[DIM*DIM];
__device__ __half g_qh [SEQ*QKLD],  g_ql [SEQ*QKLD];
__device__ __half g_kh [SEQ*QKLD],  g_kl [SEQ*QKLD];
__device__ __half g_vh [SEQ*DIM],   g_vl [SEQ*DIM];
__device__ __half g_vth[DIM*SEQ],   g_vtl[DIM*SEQ];
__device__ float  g_s[(long long)NH*SEQ*SEQ];
__device__ __half g_p[(long long)NH*SEQ*SEQ];
__device__ __half g_oh [SEQ*DIM],   g_ol [SEQ*DIM];

// ---------------------------------------------------------------------------
static __device__ __forceinline__ uint32_t s2u(const void* p) {
    uint32_t a;
    asm("{ .reg .u64 t; cvta.to.shared.u64 t, %1; cvt.u32.u64 %0, t; }" : "=r"(a) : "l"(p));
    return a;
}
#define CPA16(dst, src) \
    asm volatile("cp.async.cg.shared.global [%0], [%1], 16;" :: "r"(dst), "l"(src))
#define CPCOMMIT() asm volatile("cp.async.commit_group;" ::: "memory")
#define CPWAIT0()  asm volatile("cp.async.wait_group 0;" ::: "memory")

#define LDMX4(r0, r1, r2, r3, a) \
    asm volatile("ldmatrix.sync.aligned.m8n8.x4.shared.b16 {%0,%1,%2,%3}, [%4];" \
                 : "=r"(r0), "=r"(r1), "=r"(r2), "=r"(r3) : "r"(a))

#define MMA16816(d, a, b) \
    asm volatile("mma.sync.aligned.m16n8k16.row.col.f32.f16.f16.f32 " \
                 "{%0,%1,%2,%3},{%4,%5,%6,%7},{%8,%9},{%0,%1,%2,%3};" \
                 : "+f"((d)[0]), "+f"((d)[1]), "+f"((d)[2]), "+f"((d)[3]) \
                 : "r"((a)[0]), "r"((a)[1]), "r"((a)[2]), "r"((a)[3]), \
                   "r"((b)[0]), "r"((b)[1]))

// ---------------------------------------------------------------------------
// HMMA split-fp16 GEMM:  C = A * B^T  (both operands K-major)
//   Phases (K concatenation): AhBh [+ AlBh if ASPL] [+ AhBl if BSPL]
//   Tile 128x128, 256 thr, warp tile 32x64, K-stage 32, cp.async double buffer.
//   CSKIP: skip blocks above diagonal.  KLIM: k <= m0+128.
//   CHALF: write split-fp16 (Ch,Cl) else fp32.
// Smem: per stage per operand 128 rows x 80B (64B data + 16B pad).
// ---------------------------------------------------------------------------
template<bool ASPL, bool BSPL, bool CSKIP, bool KLIM, bool CHALF>
__global__ void __launch_bounds__(256)
hgemm(const __half* __restrict__ Ah, const __half* __restrict__ Al,
      const __half* __restrict__ Bh, const __half* __restrict__ Bl,
      void* __restrict__ Cv, __half* __restrict__ Cl,
      int K, int lda, int ldb, int ldc,
      long long sA, long long sB, long long sC)
{
    const int m0 = blockIdx.y * 128;
    const int n0 = blockIdx.x * 128;
    if (CSKIP && n0 > m0) return;

    __shared__ __align__(1024) char smem[4 * 10240];
    const uint32_t sb = s2u(smem);

    const int tid = threadIdx.x;
    const int w = tid >> 5, l = tid & 31;
    const int wm = w & 3, wn = w >> 2;

    const __half* Aph[3];
    const __half* Bph[3];
    int nph = 1;
    {
        const __half* Ahz = Ah + (long long)blockIdx.z * sA;
        const __half* Bhz = Bh + (long long)blockIdx.z * sB;
        Aph[0] = Ahz; Bph[0] = Bhz;
        if (ASPL) { Aph[nph] = Al + (long long)blockIdx.z * sA; Bph[nph] = Bhz; nph++; }
        if (BSPL) { Aph[nph] = Ahz; Bph[nph] = Bl + (long long)blockIdx.z * sB; nph++; }
    }

    const int kend = KLIM ? min(K, m0 + 128) : K;
    const int base_nst = kend >> 5;
    const int nst = nph * base_nst;

    auto load_stage = [&](int s, int buf) {
        const int phase = s / base_nst;
        const int k0 = (s - phase * base_nst) << 5;
        const __half* Ag = Aph[phase] + (long long)m0 * lda + k0;
        const __half* Bg = Bph[phase] + (long long)n0 * ldb + k0;
        const uint32_t ab = sb + buf * 20480;
        const uint32_t bb = ab + 10240;
        #pragma unroll
        for (int i = 0; i < 2; i++) {
            const int ch = tid + (i << 8);
            const int row = ch >> 2;
            const int cb = (ch & 3) << 4;          // byte offset within 64B row
            CPA16(ab + row * 80 + cb, (const char*)(Ag + (long long)row * lda) + cb);
            CPA16(bb + row * 80 + cb, (const char*)(Bg + (long long)row * ldb) + cb);
        }
        CPCOMMIT();
    };

    float acc[2][8][4];
    #pragma unroll
    for (int i = 0; i < 2; i++)
        #pragma unroll
        for (int j = 0; j < 8; j++)
            #pragma unroll
            for (int c = 0; c < 4; c++) acc[i][j][c] = 0.f;

    load_stage(0, 0);
    int buf = 0;
    for (int s = 0; s < nst; s++) {
        CPWAIT0();
        __syncthreads();
        if (s + 1 < nst) load_stage(s + 1, buf ^ 1);

        const uint32_t ab = sb + buf * 20480;
        const uint32_t bb = ab + 10240;
        #pragma unroll
        for (int kt = 0; kt < 2; kt++) {
            uint32_t a[2][4], b[8][2];
            #pragma unroll
            for (int mt = 0; mt < 2; mt++) {
                const int row = wm * 32 + mt * 16 + (l & 7) + ((l >> 3) & 1) * 8;
                const int kb  = kt * 32 + ((l >> 4) & 1) * 16;
                LDMX4(a[mt][0], a[mt][1], a[mt][2], a[mt][3], ab + row * 80 + kb);
            }
            #pragma unroll
            for (int np = 0; np < 4; np++) {
                const int row = wn * 64 + np * 16 + (l & 7) + ((l >> 4) & 1) * 8;
                const int kb  = kt * 32 + ((l >> 3) & 1) * 16;
                LDMX4(b[np*2][0], b[np*2][1], b[np*2+1][0], b[np*2+1][1],
                      bb + row * 80 + kb);
            }
            #pragma unroll
            for (int mt = 0; mt < 2; mt++)
                #pragma unroll
                for (int nt = 0; nt < 8; nt++)
                    MMA16816(acc[mt][nt], a[mt], b[nt]);
        }
        buf ^= 1;
    }

    // ----- epilogue -----
    #pragma unroll
    for (int mt = 0; mt < 2; mt++) {
        #pragma unroll
        for (int nt = 0; nt < 8; nt++) {
            const int row = m0 + wm * 32 + mt * 16 + (l >> 2);
            const int col = n0 + wn * 64 + nt * 8 + (l & 3) * 2;
            const float c0 = acc[mt][nt][0], c1 = acc[mt][nt][1];
            const float c2 = acc[mt][nt][2], c3 = acc[mt][nt][3];
            if (CHALF) {
                __half* Ch  = (__half*)Cv + (long long)blockIdx.z * sC;
                __half* Cll = Cl + (long long)blockIdx.z * sC;
                __half h0 = __float2half_rn(c0), h1 = __float2half_rn(c1);
                *(__half2*)(Ch  + (long long)row * ldc + col) = __halves2half2(h0, h1);
                *(__half2*)(Cll + (long long)row * ldc + col) =
                    __halves2half2(__float2half_rn(c0 - __half2float(h0)),
                                   __float2half_rn(c1 - __half2float(h1)));
                __half h2 = __float2half_rn(c2), h3 = __float2half_rn(c3);
                *(__half2*)(Ch  + (long long)(row + 8) * ldc + col) = __halves2half2(h2, h3);
                *(__half2*)(Cll + (long long)(row + 8) * ldc + col) =
                    __halves2half2(__float2half_rn(c2 - __half2float(h2)),
                                   __float2half_rn(c3 - __half2float(h3)));
            } else {
                float* Cf = (float*)Cv + (long long)blockIdx.z * sC;
                *(float2*)(Cf + (long long)row * ldc + col)       = make_float2(c0, c1);
                *(float2*)(Cf + (long long)(row + 8) * ldc + col) = make_float2(c2, c3);
            }
        }
    }
}

// ---------------------------------------------------------------------------
__global__ void f2hsplit(const float* __restrict__ in, __half* __restrict__ oh,
                         __half* __restrict__ ol, int n)
{
    int i = blockIdx.x * 256 + threadIdx.x;
    if (i >= n) return;
    float v = in[i];
    __half h = __float2half_rn(v);
    oh[i] = h;
    ol[i] = __float2half_rn(v - __half2float(h));
}

// ---------------------------------------------------------------------------
__global__ void rope_kernel(__half* Qh, __half* Ql, __half* Kh, __half* Kl,
                            const float* __restrict__ cosT, const float* __restrict__ sinT)
{
    int idx = blockIdx.x * blockDim.x + threadIdx.x;
    if (idx >= SEQ * NH * (ROPE / 2)) return;
    int i = idx & 31, h = (idx >> 5) & 15, s = idx >> 9;
    float c = cosT[s * 32 + i], sn = sinT[s * 32 + i];
    long long base = (long long)s * QKLD + h * HD + NOPE + 2 * i;
    float a, b, ra, rb; __half hh;
    a = __half2float(Qh[base])   + __half2float(Ql[base]);
    b = __half2float(Qh[base+1]) + __half2float(Ql[base+1]);
    ra = a * c - b * sn; rb = a * sn + b * c;
    hh = __float2half_rn(ra); Qh[base]   = hh; Ql[base]   = __float2half_rn(ra - __half2float(hh));
    hh = __float2half_rn(rb); Qh[base+1] = hh; Ql[base+1] = __float2half_rn(rb - __half2float(hh));
    a = __half2float(Kh[base])   + __half2float(Kl[base]);
    b = __half2float(Kh[base+1]) + __half2float(Kl[base+1]);
    ra = a * c - b * sn; rb = a * sn + b * c;
    hh = __float2half_rn(ra); Kh[base]   = hh; Kl[base]   = __float2half_rn(ra - __half2float(hh));
    hh = __float2half_rn(rb); Kh[base+1] = hh; Kl[base+1] = __float2half_rn(rb - __half2float(hh));
}

// ---------------------------------------------------------------------------
__global__ void transpose_h(const __half* __restrict__ in, __half* __restrict__ out)
{
    __shared__ __half t[32][33];
    int x = blockIdx.x * 32 + threadIdx.x;
    int y = blockIdx.y * 32 + threadIdx.y;
    #pragma unroll
    for (int j = 0; j < 32; j += 8)
        t[threadIdx.y + j][threadIdx.x] = in[(long long)(y + j) * DIM + x];
    __syncthreads();
    x = blockIdx.y * 32 + threadIdx.x;
    y = blockIdx.x * 32 + threadIdx.y;
    #pragma unroll
    for (int j = 0; j < 32; j += 8)
        out[(long long)(y + j) * SEQ + x] = t[threadIdx.x][threadIdx.y + j];
}

// ---------------------------------------------------------------------------
__global__ void softmax_causal(const float* __restrict__ S, __half* __restrict__ P, float scale)
{
    const int s = blockIdx.x, h = blockIdx.y;
    const float* row = S + ((long long)h * SEQ + s) * SEQ;
    __half* prow = P + ((long long)h * SEQ + s) * SEQ;
    const int n = s + 1;
    const int tid = threadIdx.x;
    __shared__ float buf[SEQ];
    __shared__ float red[8];

    float m = -1e30f;
    for (int t = tid; t < n; t += 256) { float v = row[t]; buf[t] = v; m = fmaxf(m, v); }
    #pragma unroll
    for (int o = 16; o; o >>= 1) m = fmaxf(m, __shfl_xor_sync(0xffffffffu, m, o));
    if ((tid & 31) == 0) red[tid >> 5] = m;
    __syncthreads();
    if (tid < 8) {
        float v = red[tid];
        #pragma unroll
        for (int o = 4; o; o >>= 1) v = fmaxf(v, __shfl_xor_sync(0xffu, v, o));
        if (tid == 0) red[0] = v;
    }
    __syncthreads();
    m = red[0];
    __syncthreads();

    float sum = 0.f;
    for (int t = tid; t < n; t += 256) {
        float e = __expf((buf[t] - m) * scale);
        buf[t] = e; sum += e;
    }
    #pragma unroll
    for (int o = 16; o; o >>= 1) sum += __shfl_xor_sync(0xffffffffu, sum, o);
    if ((tid & 31) == 0) red[tid >> 5] = sum;
    __syncthreads();
    if (tid < 8) {
        float v = red[tid];
        #pragma unroll
        for (int o = 4; o; o >>= 1) v += __shfl_xor_sync(0xffu, v, o);
        if (tid == 0) red[0] = v;
    }
    __syncthreads();
    const float inv = 1.f / red[0];
    __syncthreads();

    for (int t = tid; t < SEQ; t += 256)
        prow[t] = (t < n) ? __float2half_rn(buf[t] * inv) : __float2half_rn(0.f);
}

// ---------------------------------------------------------------------------
extern "C" void kernel_launch(void* const* d_in, const int* in_sizes, int n_in,
                              void* d_out, int out_size)
{
    const float* x  = (const float*)d_in[0];
    const float* wq = (const float*)d_in[1];
    const float* wk = (const float*)d_in[2];
    const float* wv = (const float*)d_in[3];
    const float* wo = (const float*)d_in[4];
    const float* fc = (const float*)d_in[5];
    const float* fs = (const float*)d_in[6];
    float* out = (float*)d_out;

    __half *xh, *xl, *wqh, *wql, *wkh, *wkl, *wvh, *wvl, *woh, *wol;
    __half *qh, *ql, *kh, *kl, *vh, *vl, *vth, *vtl, *p, *oh, *ol;
    float* sc;
    cudaGetSymbolAddress((void**)&xh, g_xh);   cudaGetSymbolAddress((void**)&xl, g_xl);
    cudaGetSymbolAddress((void**)&wqh, g_wqh); cudaGetSymbolAddress((void**)&wql, g_wql);
    cudaGetSymbolAddress((void**)&wkh, g_wkh); cudaGetSymbolAddress((void**)&wkl, g_wkl);
    cudaGetSymbolAddress((void**)&wvh, g_wvh); cudaGetSymbolAddress((void**)&wvl, g_wvl);
    cudaGetSymbolAddress((void**)&woh, g_woh); cudaGetSymbolAddress((void**)&wol, g_wol);
    cudaGetSymbolAddress((void**)&qh, g_qh);   cudaGetSymbolAddress((void**)&ql, g_ql);
    cudaGetSymbolAddress((void**)&kh, g_kh);   cudaGetSymbolAddress((void**)&kl, g_kl);
    cudaGetSymbolAddress((void**)&vh, g_vh);   cudaGetSymbolAddress((void**)&vl, g_vl);
    cudaGetSymbolAddress((void**)&vth, g_vth); cudaGetSymbolAddress((void**)&vtl, g_vtl);
    cudaGetSymbolAddress((void**)&p, g_p);
    cudaGetSymbolAddress((void**)&oh, g_oh);   cudaGetSymbolAddress((void**)&ol, g_ol);
    cudaGetSymbolAddress((void**)&sc, g_s);

    // split-fp16 conversions
    f2hsplit<<<SEQ * DIM / 256, 256>>>(x, xh, xl, SEQ * DIM);
    f2hsplit<<<QKLD * DIM / 256, 256>>>(wq, wqh, wql, QKLD * DIM);
    f2hsplit<<<QKLD * DIM / 256, 256>>>(wk, wkh, wkl, QKLD * DIM);
    f2hsplit<<<DIM * DIM / 256, 256>>>(wv, wvh, wvl, DIM * DIM);
    f2hsplit<<<DIM * DIM / 256, 256>>>(wo, woh, wol, DIM * DIM);

    // projections (split x split, 3-phase), split-fp16 outputs
    hgemm<1,1,0,0,1><<<dim3(QKLD / 128, SEQ / 128), 256>>>(
        xh, xl, wqh, wql, qh, ql, DIM, DIM, DIM, QKLD, 0, 0, 0);
    hgemm<1,1,0,0,1><<<dim3(QKLD / 128, SEQ / 128), 256>>>(
        xh, xl, wkh, wkl, kh, kl, DIM, DIM, DIM, QKLD, 0, 0, 0);
    hgemm<1,1,0,0,1><<<dim3(DIM / 128, SEQ / 128), 256>>>(
        xh, xl, wvh, wvl, vh, vl, DIM, DIM, DIM, DIM, 0, 0, 0);

    // RoPE
    rope_kernel<<<(SEQ * NH * 32 + 255) / 256, 256>>>(qh, ql, kh, kl, fc, fs);

    // V transpose -> [DIM][SEQ] K-major for PV
    transpose_h<<<dim3(64, 64), dim3(32, 8)>>>(vh, vth);
    transpose_h<<<dim3(64, 64), dim3(32, 8)>>>(vl, vtl);

    // scores (causal block skip), fp32 out
    hgemm<1,1,1,0,0><<<dim3(SEQ / 128, SEQ / 128, NH), 256>>>(
        qh, ql, kh, kl, sc, nullptr, HD, QKLD, QKLD, SEQ,
        HD, HD, (long long)SEQ * SEQ);

    // softmax -> fp16 probs
    softmax_causal<<<dim3(SEQ, NH), 256>>>(sc, p, rsqrtf((float)HD));

    // PV (causal K-limit): probs single fp16, V split (2-phase)
    hgemm<0,1,0,1,1><<<dim3(1, SEQ / 128, NH), 256>>>(
        p, nullptr, vth, vtl, oh, ol, SEQ, SEQ, SEQ, DIM,
        (long long)SEQ * SEQ, (long long)VD * SEQ, VD);

    // output projection, fp32 out
    hgemm<1,1,0,0,0><<<dim3(DIM / 128, SEQ / 128), 256>>>(
        oh, ol, woh, wol, out, nullptr, DIM, DIM, DIM, DIM, 0, 0, 0);
}

// round 4
// speedup vs baseline: 2.3408x; 1.0860x over previous
#include <cuda_runtime.h>
#include <cuda_fp16.h>
#include <cstdint>
#include <math.h>

#define SEQ 2048
#define DIM 2048
#define NH 16
#define HD 192
#define NOPE 128
#define ROPE 64
#define VD 128
#define QKLD (NH*HD)   // 3072

// ---------------------------------------------------------------------------
// split-fp16 scratch (allocation-free __device__ globals)
// ---------------------------------------------------------------------------
__device__ __half g_xh [SEQ*DIM],   g_xl [SEQ*DIM];
__device__ __half g_wqh[QKLD*DIM],  g_wql[QKLD*DIM];
__device__ __half g_wkh[QKLD*DIM],  g_wkl[QKLD*DIM];
__device__ __half g_wvh[DIM*DIM],   g_wvl[DIM*DIM];
__device__ __half g_woh[DIM*DIM],   g_wol[DIM*DIM];
__device__ __half g_qh [SEQ*QKLD],  g_ql [SEQ*QKLD];
__device__ __half g_kh [SEQ*QKLD],  g_kl [SEQ*QKLD];
__device__ __half g_vh [SEQ*DIM],   g_vl [SEQ*DIM];
__device__ __half g_vth[DIM*SEQ],   g_vtl[DIM*SEQ];
__device__ float  g_s[(long long)NH*SEQ*SEQ];
__device__ __half g_p[(long long)NH*SEQ*SEQ];
__device__ __half g_oh [SEQ*DIM],   g_ol [SEQ*DIM];

// ---------------------------------------------------------------------------
static __device__ __forceinline__ uint32_t s2u(const void* p) {
    uint32_t a;
    asm("{ .reg .u64 t; cvta.to.shared.u64 t, %1; cvt.u32.u64 %0, t; }" : "=r"(a) : "l"(p));
    return a;
}
#define CPA16(dst, src) \
    asm volatile("cp.async.cg.shared.global [%0], [%1], 16;" :: "r"(dst), "l"(src))
#define CPCOMMIT() asm volatile("cp.async.commit_group;" ::: "memory")
#define CPWAIT2()  asm volatile("cp.async.wait_group 2;" ::: "memory")

#define LDMX4(r0, r1, r2, r3, a) \
    asm volatile("ldmatrix.sync.aligned.m8n8.x4.shared.b16 {%0,%1,%2,%3}, [%4];" \
                 : "=r"(r0), "=r"(r1), "=r"(r2), "=r"(r3) : "r"(a))

#define MMA16816(d, a, b) \
    asm volatile("mma.sync.aligned.m16n8k16.row.col.f32.f16.f16.f32 " \
                 "{%0,%1,%2,%3},{%4,%5,%6,%7},{%8,%9},{%0,%1,%2,%3};" \
                 : "+f"((d)[0]), "+f"((d)[1]), "+f"((d)[2]), "+f"((d)[3]) \
                 : "r"((a)[0]), "r"((a)[1]), "r"((a)[2]), "r"((a)[3]), \
                   "r"((b)[0]), "r"((b)[1]))

// ---------------------------------------------------------------------------
// HMMA split-fp16 GEMM:  C = A * B^T  (both operands K-major)
//   Phases (K concatenation): AhBh [+ AlBh if ASPL] [+ AhBl if BSPL]
//   Tile 128x128, 256 thr, warp tile 32x64, K-stage 32.
//   4-stage cp.async pipeline (wait_group 2; empty commits at tail).
//   CSKIP: skip blocks above diagonal.  KLIM: k <= m0+128.
//   CHALF: write split-fp16 (Ch,Cl) else fp32.
// Smem: 4 stages x (A 128x80B + B 128x80B) = 81920 B dynamic.
// ---------------------------------------------------------------------------
template<bool ASPL, bool BSPL, bool CSKIP, bool KLIM, bool CHALF>
__global__ void __launch_bounds__(256)
hgemm(const __half* __restrict__ Ah, const __half* __restrict__ Al,
      const __half* __restrict__ Bh, const __half* __restrict__ Bl,
      void* __restrict__ Cv, __half* __restrict__ Cl,
      int K, int lda, int ldb, int ldc,
      long long sA, long long sB, long long sC)
{
    const int m0 = blockIdx.y * 128;
    const int n0 = blockIdx.x * 128;
    if (CSKIP && n0 > m0) return;

    extern __shared__ __align__(1024) char smem[];
    const uint32_t sb = s2u(smem);

    const int tid = threadIdx.x;
    const int w = tid >> 5, l = tid & 31;
    const int wm = w & 3, wn = w >> 2;

    const __half* Aph[3];
    const __half* Bph[3];
    int nph = 1;
    {
        const __half* Ahz = Ah + (long long)blockIdx.z * sA;
        const __half* Bhz = Bh + (long long)blockIdx.z * sB;
        Aph[0] = Ahz; Bph[0] = Bhz;
        if (ASPL) { Aph[nph] = Al + (long long)blockIdx.z * sA; Bph[nph] = Bhz; nph++; }
        if (BSPL) { Aph[nph] = Ahz; Bph[nph] = Bl + (long long)blockIdx.z * sB; nph++; }
    }

    const int kend = KLIM ? min(K, m0 + 128) : K;
    const int base_nst = kend >> 5;
    const int nst = nph * base_nst;

    auto load_stage = [&](int s, int buf) {
        const int phase = s / base_nst;
        const int k0 = (s - phase * base_nst) << 5;
        const __half* Ag = Aph[phase] + (long long)m0 * lda + k0;
        const __half* Bg = Bph[phase] + (long long)n0 * ldb + k0;
        const uint32_t ab = sb + buf * 20480;
        const uint32_t bb = ab + 10240;
        #pragma unroll
        for (int i = 0; i < 2; i++) {
            const int ch = tid + (i << 8);
            const int row = ch >> 2;
            const int cb = (ch & 3) << 4;          // byte offset within 64B row
            CPA16(ab + row * 80 + cb, (const char*)(Ag + (long long)row * lda) + cb);
            CPA16(bb + row * 80 + cb, (const char*)(Bg + (long long)row * ldb) + cb);
        }
    };

    float acc[2][8][4];
    #pragma unroll
    for (int i = 0; i < 2; i++)
        #pragma unroll
        for (int j = 0; j < 8; j++)
            #pragma unroll
            for (int c = 0; c < 4; c++) acc[i][j][c] = 0.f;

    // prologue: stages 0..2 in flight
    #pragma unroll
    for (int i = 0; i < 3; i++) {
        if (i < nst) load_stage(i, i);
        CPCOMMIT();
    }

    for (int s = 0; s < nst; s++) {
        CPWAIT2();                 // stage s copy complete (<=2 groups pending)
        __syncthreads();           // also protects buffer (s+3)&3 from iter s-1 readers
        if (s + 3 < nst) load_stage(s + 3, (s + 3) & 3);
        CPCOMMIT();                // real or empty group: keeps group count uniform

        const uint32_t ab = sb + (s & 3) * 20480;
        const uint32_t bb = ab + 10240;
        #pragma unroll
        for (int kt = 0; kt < 2; kt++) {
            uint32_t a[2][4], b[8][2];
            #pragma unroll
            for (int mt = 0; mt < 2; mt++) {
                const int row = wm * 32 + mt * 16 + (l & 7) + ((l >> 3) & 1) * 8;
                const int kb  = kt * 32 + ((l >> 4) & 1) * 16;
                LDMX4(a[mt][0], a[mt][1], a[mt][2], a[mt][3], ab + row * 80 + kb);
            }
            #pragma unroll
            for (int np = 0; np < 4; np++) {
                const int row = wn * 64 + np * 16 + (l & 7) + ((l >> 4) & 1) * 8;
                const int kb  = kt * 32 + ((l >> 3) & 1) * 16;
                LDMX4(b[np*2][0], b[np*2][1], b[np*2+1][0], b[np*2+1][1],
                      bb + row * 80 + kb);
            }
            #pragma unroll
            for (int mt = 0; mt < 2; mt++)
                #pragma unroll
                for (int nt = 0; nt < 8; nt++)
                    MMA16816(acc[mt][nt], a[mt], b[nt]);
        }
    }

    // ----- epilogue -----
    #pragma unroll
    for (int mt = 0; mt < 2; mt++) {
        #pragma unroll
        for (int nt = 0; nt < 8; nt++) {
            const int row = m0 + wm * 32 + mt * 16 + (l >> 2);
            const int col = n0 + wn * 64 + nt * 8 + (l & 3) * 2;
            const float c0 = acc[mt][nt][0], c1 = acc[mt][nt][1];
            const float c2 = acc[mt][nt][2], c3 = acc[mt][nt][3];
            if (CHALF) {
                __half* Ch  = (__half*)Cv + (long long)blockIdx.z * sC;
                __half* Cll = Cl + (long long)blockIdx.z * sC;
                __half h0 = __float2half_rn(c0), h1 = __float2half_rn(c1);
                *(__half2*)(Ch  + (long long)row * ldc + col) = __halves2half2(h0, h1);
                *(__half2*)(Cll + (long long)row * ldc + col) =
                    __halves2half2(__float2half_rn(c0 - __half2float(h0)),
                                   __float2half_rn(c1 - __half2float(h1)));
                __half h2 = __float2half_rn(c2), h3 = __float2half_rn(c3);
                *(__half2*)(Ch  + (long long)(row + 8) * ldc + col) = __halves2half2(h2, h3);
                *(__half2*)(Cll + (long long)(row + 8) * ldc + col) =
                    __halves2half2(__float2half_rn(c2 - __half2float(h2)),
                                   __float2half_rn(c3 - __half2float(h3)));
            } else {
                float* Cf = (float*)Cv + (long long)blockIdx.z * sC;
                *(float2*)(Cf + (long long)row * ldc + col)       = make_float2(c0, c1);
                *(float2*)(Cf + (long long)(row + 8) * ldc + col) = make_float2(c2, c3);
            }
        }
    }
}

// ---------------------------------------------------------------------------
// fp32 -> split-fp16, float4 vectorized (n divisible by 1024)
// ---------------------------------------------------------------------------
__global__ void f2hsplit(const float* __restrict__ in, __half* __restrict__ oh,
                         __half* __restrict__ ol, int n)
{
    int i = (blockIdx.x * 256 + threadIdx.x) * 4;
    if (i >= n) return;
    float4 v = *(const float4*)(in + i);
    __half hx = __float2half_rn(v.x), hy = __float2half_rn(v.y);
    __half hz = __float2half_rn(v.z), hw = __float2half_rn(v.w);
    *(__half2*)(oh + i)     = __halves2half2(hx, hy);
    *(__half2*)(oh + i + 2) = __halves2half2(hz, hw);
    *(__half2*)(ol + i) = __halves2half2(
        __float2half_rn(v.x - __half2float(hx)), __float2half_rn(v.y - __half2float(hy)));
    *(__half2*)(ol + i + 2) = __halves2half2(
        __float2half_rn(v.z - __half2float(hz)), __float2half_rn(v.w - __half2float(hw)));
}

// ---------------------------------------------------------------------------
__global__ void rope_kernel(__half* Qh, __half* Ql, __half* Kh, __half* Kl,
                            const float* __restrict__ cosT, const float* __restrict__ sinT)
{
    int idx = blockIdx.x * blockDim.x + threadIdx.x;
    if (idx >= SEQ * NH * (ROPE / 2)) return;
    int i = idx & 31, h = (idx >> 5) & 15, s = idx >> 9;
    float c = cosT[s * 32 + i], sn = sinT[s * 32 + i];
    long long base = (long long)s * QKLD + h * HD + NOPE + 2 * i;
    float a, b, ra, rb; __half hh;
    a = __half2float(Qh[base])   + __half2float(Ql[base]);
    b = __half2float(Qh[base+1]) + __half2float(Ql[base+1]);
    ra = a * c - b * sn; rb = a * sn + b * c;
    hh = __float2half_rn(ra); Qh[base]   = hh; Ql[base]   = __float2half_rn(ra - __half2float(hh));
    hh = __float2half_rn(rb); Qh[base+1] = hh; Ql[base+1] = __float2half_rn(rb - __half2float(hh));
    a = __half2float(Kh[base])   + __half2float(Kl[base]);
    b = __half2float(Kh[base+1]) + __half2float(Kl[base+1]);
    ra = a * c - b * sn; rb = a * sn + b * c;
    hh = __float2half_rn(ra); Kh[base]   = hh; Kl[base]   = __float2half_rn(ra - __half2float(hh));
    hh = __float2half_rn(rb); Kh[base+1] = hh; Kl[base+1] = __float2half_rn(rb - __half2float(hh));
}

// ---------------------------------------------------------------------------
__global__ void transpose_h(const __half* __restrict__ in, __half* __restrict__ out)
{
    __shared__ __half t[32][33];
    int x = blockIdx.x * 32 + threadIdx.x;
    int y = blockIdx.y * 32 + threadIdx.y;
    #pragma unroll
    for (int j = 0; j < 32; j += 8)
        t[threadIdx.y + j][threadIdx.x] = in[(long long)(y + j) * DIM + x];
    __syncthreads();
    x = blockIdx.y * 32 + threadIdx.x;
    y = blockIdx.x * 32 + threadIdx.y;
    #pragma unroll
    for (int j = 0; j < 32; j += 8)
        out[(long long)(y + j) * SEQ + x] = t[threadIdx.x][threadIdx.y + j];
}

// ---------------------------------------------------------------------------
__global__ void softmax_causal(const float* __restrict__ S, __half* __restrict__ P, float scale)
{
    const int s = blockIdx.x, h = blockIdx.y;
    const float* row = S + ((long long)h * SEQ + s) * SEQ;
    __half* prow = P + ((long long)h * SEQ + s) * SEQ;
    const int n = s + 1;
    const int tid = threadIdx.x;
    __shared__ float buf[SEQ];
    __shared__ float red[8];

    float m = -1e30f;
    for (int t = tid; t < n; t += 256) { float v = row[t]; buf[t] = v; m = fmaxf(m, v); }
    #pragma unroll
    for (int o = 16; o; o >>= 1) m = fmaxf(m, __shfl_xor_sync(0xffffffffu, m, o));
    if ((tid & 31) == 0) red[tid >> 5] = m;
    __syncthreads();
    if (tid < 8) {
        float v = red[tid];
        #pragma unroll
        for (int o = 4; o; o >>= 1) v = fmaxf(v, __shfl_xor_sync(0xffu, v, o));
        if (tid == 0) red[0] = v;
    }
    __syncthreads();
    m = red[0];
    __syncthreads();

    float sum = 0.f;
    for (int t = tid; t < n; t += 256) {
        float e = __expf((buf[t] - m) * scale);
        buf[t] = e; sum += e;
    }
    #pragma unroll
    for (int o = 16; o; o >>= 1) sum += __shfl_xor_sync(0xffffffffu, sum, o);
    if ((tid & 31) == 0) red[tid >> 5] = sum;
    __syncthreads();
    if (tid < 8) {
        float v = red[tid];
        #pragma unroll
        for (int o = 4; o; o >>= 1) v += __shfl_xor_sync(0xffu, v, o);
        if (tid == 0) red[0] = v;
    }
    __syncthreads();
    const float inv = 1.f / red[0];
    __syncthreads();

    for (int t = tid * 2; t < SEQ; t += 512) {
        float a = (t     < n) ? buf[t]     * inv : 0.f;
        float b = (t + 1 < n) ? buf[t + 1] * inv : 0.f;
        *(__half2*)(prow + t) = __halves2half2(__float2half_rn(a), __float2half_rn(b));
    }
}

// ---------------------------------------------------------------------------
extern "C" void kernel_launch(void* const* d_in, const int* in_sizes, int n_in,
                              void* d_out, int out_size)
{
    const float* x  = (const float*)d_in[0];
    const float* wq = (const float*)d_in[1];
    const float* wk = (const float*)d_in[2];
    const float* wv = (const float*)d_in[3];
    const float* wo = (const float*)d_in[4];
    const float* fc = (const float*)d_in[5];
    const float* fs = (const float*)d_in[6];
    float* out = (float*)d_out;

    __half *xh, *xl, *wqh, *wql, *wkh, *wkl, *wvh, *wvl, *woh, *wol;
    __half *qh, *ql, *kh, *kl, *vh, *vl, *vth, *vtl, *p, *oh, *ol;
    float* sc;
    cudaGetSymbolAddress((void**)&xh, g_xh);   cudaGetSymbolAddress((void**)&xl, g_xl);
    cudaGetSymbolAddress((void**)&wqh, g_wqh); cudaGetSymbolAddress((void**)&wql, g_wql);
    cudaGetSymbolAddress((void**)&wkh, g_wkh); cudaGetSymbolAddress((void**)&wkl, g_wkl);
    cudaGetSymbolAddress((void**)&wvh, g_wvh); cudaGetSymbolAddress((void**)&wvl, g_wvl);
    cudaGetSymbolAddress((void**)&woh, g_woh); cudaGetSymbolAddress((void**)&wol, g_wol);
    cudaGetSymbolAddress((void**)&qh, g_qh);   cudaGetSymbolAddress((void**)&ql, g_ql);
    cudaGetSymbolAddress((void**)&kh, g_kh);   cudaGetSymbolAddress((void**)&kl, g_kl);
    cudaGetSymbolAddress((void**)&vh, g_vh);   cudaGetSymbolAddress((void**)&vl, g_vl);
    cudaGetSymbolAddress((void**)&vth, g_vth); cudaGetSymbolAddress((void**)&vtl, g_vtl);
    cudaGetSymbolAddress((void**)&p, g_p);
    cudaGetSymbolAddress((void**)&oh, g_oh);   cudaGetSymbolAddress((void**)&ol, g_ol);
    cudaGetSymbolAddress((void**)&sc, g_s);

    const int SMEM = 4 * 20480;  // 81920
    cudaFuncSetAttribute((const void*)hgemm<1,1,0,0,1>, cudaFuncAttributeMaxDynamicSharedMemorySize, SMEM);
    cudaFuncSetAttribute((const void*)hgemm<1,1,1,0,0>, cudaFuncAttributeMaxDynamicSharedMemorySize, SMEM);
    cudaFuncSetAttribute((const void*)hgemm<0,1,0,1,1>, cudaFuncAttributeMaxDynamicSharedMemorySize, SMEM);
    cudaFuncSetAttribute((const void*)hgemm<1,1,0,0,0>, cudaFuncAttributeMaxDynamicSharedMemorySize, SMEM);

    // split-fp16 conversions (x4 vectorized)
    f2hsplit<<<SEQ * DIM / 1024, 256>>>(x, xh, xl, SEQ * DIM);
    f2hsplit<<<QKLD * DIM / 1024, 256>>>(wq, wqh, wql, QKLD * DIM);
    f2hsplit<<<QKLD * DIM / 1024, 256>>>(wk, wkh, wkl, QKLD * DIM);
    f2hsplit<<<DIM * DIM / 1024, 256>>>(wv, wvh, wvl, DIM * DIM);
    f2hsplit<<<DIM * DIM / 1024, 256>>>(wo, woh, wol, DIM * DIM);

    // projections (split x split, 3-phase), split-fp16 outputs
    hgemm<1,1,0,0,1><<<dim3(QKLD / 128, SEQ / 128), 256, SMEM>>>(
        xh, xl, wqh, wql, qh, ql, DIM, DIM, DIM, QKLD, 0, 0, 0);
    hgemm<1,1,0,0,1><<<dim3(QKLD / 128, SEQ / 128), 256, SMEM>>>(
        xh, xl, wkh, wkl, kh, kl, DIM, DIM, DIM, QKLD, 0, 0, 0);
    hgemm<1,1,0,0,1><<<dim3(DIM / 128, SEQ / 128), 256, SMEM>>>(
        xh, xl, wvh, wvl, vh, vl, DIM, DIM, DIM, DIM, 0, 0, 0);

    // RoPE
    rope_kernel<<<(SEQ * NH * 32 + 255) / 256, 256>>>(qh, ql, kh, kl, fc, fs);

    // V transpose -> [DIM][SEQ] K-major for PV
    transpose_h<<<dim3(64, 64), dim3(32, 8)>>>(vh, vth);
    transpose_h<<<dim3(64, 64), dim3(32, 8)>>>(vl, vtl);

    // scores (causal block skip), fp32 out
    hgemm<1,1,1,0,0><<<dim3(SEQ / 128, SEQ / 128, NH), 256, SMEM>>>(
        qh, ql, kh, kl, sc, nullptr, HD, QKLD, QKLD, SEQ,
        HD, HD, (long long)SEQ * SEQ);

    // softmax -> fp16 probs
    softmax_causal<<<dim3(SEQ, NH), 256>>>(sc, p, rsqrtf((float)HD));

    // PV (causal K-limit): probs single fp16, V split (2-phase)
    hgemm<0,1,0,1,1><<<dim3(1, SEQ / 128, NH), 256, SMEM>>>(
        p, nullptr, vth, vtl, oh, ol, SEQ, SEQ, SEQ, DIM,
        (long long)SEQ * SEQ, (long long)VD * SEQ, VD);

    // output projection, fp32 out
    hgemm<1,1,0,0,0><<<dim3(DIM / 128, SEQ / 128), 256, SMEM>>>(
        oh, ol, woh, wol, out, nullptr, DIM, DIM, DIM, DIM, 0, 0, 0);
}

// round 5
// speedup vs baseline: 3.6219x; 1.5473x over previous
#include <cuda_runtime.h>
#include <cuda_fp16.h>
#include <cstdint>
#include <math.h>

#define SEQ 2048
#define DIM 2048
#define NH 16
#define HD 192
#define NOPE 128
#define ROPE 64
#define VD 128
#define QKLD (NH*HD)   // 3072

// ---------------------------------------------------------------------------
// scratch (allocation-free __device__ globals)
// ---------------------------------------------------------------------------
__device__ __half g_xh [SEQ*DIM],   g_xl [SEQ*DIM];
__device__ __half g_wqh[QKLD*DIM];
__device__ __half g_wkh[QKLD*DIM];
__device__ __half g_wvh[DIM*DIM];
__device__ __half g_woh[DIM*DIM];
__device__ __half g_qh [SEQ*QKLD],  g_ql [SEQ*QKLD];
__device__ __half g_kh [SEQ*QKLD],  g_kl [SEQ*QKLD];
__device__ __half g_vh [SEQ*DIM],   g_vl [SEQ*DIM];
__device__ __half g_vth[DIM*SEQ],   g_vtl[DIM*SEQ];
__device__ float  g_s[(long long)NH*SEQ*SEQ];
__device__ __half g_p[(long long)NH*SEQ*SEQ];
__device__ __half g_oh [SEQ*DIM],   g_ol [SEQ*DIM];

// ---------------------------------------------------------------------------
static __device__ __forceinline__ uint32_t s2u(const void* p) {
    uint32_t a;
    asm("{ .reg .u64 t; cvta.to.shared.u64 t, %1; cvt.u32.u64 %0, t; }" : "=r"(a) : "l"(p));
    return a;
}
#define CPA16(dst, src) \
    asm volatile("cp.async.cg.shared.global [%0], [%1], 16;" :: "r"(dst), "l"(src))
#define CPCOMMIT() asm volatile("cp.async.commit_group;" ::: "memory")
#define CPWAIT1()  asm volatile("cp.async.wait_group 1;" ::: "memory")

#define LDMX4(r0, r1, r2, r3, a) \
    asm volatile("ldmatrix.sync.aligned.m8n8.x4.shared.b16 {%0,%1,%2,%3}, [%4];" \
                 : "=r"(r0), "=r"(r1), "=r"(r2), "=r"(r3) : "r"(a))

#define MMA16816(d, a, b) \
    asm volatile("mma.sync.aligned.m16n8k16.row.col.f32.f16.f16.f32 " \
                 "{%0,%1,%2,%3},{%4,%5,%6,%7},{%8,%9},{%0,%1,%2,%3};" \
                 : "+f"((d)[0]), "+f"((d)[1]), "+f"((d)[2]), "+f"((d)[3]) \
                 : "r"((a)[0]), "r"((a)[1]), "r"((a)[2]), "r"((a)[3]), \
                   "r"((b)[0]), "r"((b)[1]))

// ---------------------------------------------------------------------------
// HMMA GEMM:  C = A * B^T  (both operands K-major), 2-term split numerics.
//   acc = Ah*Bh^T  [+ Al*Bh^T if ASPL]  [+ Ah*Bl^T if BSPL]
//   All tiles of one K=32 stage loaded ONCE; MMA passes reuse smem/regs.
//   Tile 128x128, 256 thr, warp tile 32x64, 3-stage cp.async pipeline.
//   CSKIP: skip blocks above diagonal.  KLIM: k <= m0+128.
//   CHALF: write split-fp16 (Ch,Cl) else fp32.
// Smem/stage: (2+ASPL+BSPL) tiles x 128 rows x 80B = 30720 B; x3 stages.
// ---------------------------------------------------------------------------
template<bool ASPL, bool BSPL, bool CSKIP, bool KLIM, bool CHALF>
__global__ void __launch_bounds__(256, 2)
hgemm(const __half* __restrict__ Ah, const __half* __restrict__ Al,
      const __half* __restrict__ Bh, const __half* __restrict__ Bl,
      void* __restrict__ Cv, __half* __restrict__ Cl,
      int K, int lda, int ldb, int ldc,
      long long sA, long long sB, long long sC)
{
    const int m0 = blockIdx.y * 128;
    const int n0 = blockIdx.x * 128;
    if (CSKIP && n0 > m0) return;

    constexpr int NTILE = 2 + (ASPL ? 1 : 0) + (BSPL ? 1 : 0);
    constexpr int STAGE = NTILE * 10240;
    constexpr int OAL = 10240;
    constexpr int OB  = (ASPL ? 2 : 1) * 10240;
    constexpr int OBL = OB + 10240;

    extern __shared__ __align__(1024) char smem[];
    const uint32_t sb = s2u(smem);

    const int tid = threadIdx.x;
    const int w = tid >> 5, l = tid & 31;
    const int wm = w & 3, wn = w >> 2;

    const __half* Ahz = Ah + (long long)blockIdx.z * sA;
    const __half* Alz = ASPL ? Al + (long long)blockIdx.z * sA : nullptr;
    const __half* Bhz = Bh + (long long)blockIdx.z * sB;
    const __half* Blz = BSPL ? Bl + (long long)blockIdx.z * sB : nullptr;

    const int kend = KLIM ? min(K, m0 + 128) : K;
    const int nst = kend >> 5;

    // per-thread loader coords: 4 threads per 64B row chunk-group
    const int lrow = tid >> 2;             // rows lrow, lrow+64
    const int lcb  = (tid & 3) << 4;       // 16B chunk in row

    auto load_tile = [&](const __half* G, int ld, uint32_t dstbase) {
        #pragma unroll
        for (int i = 0; i < 2; i++) {
            const int row = lrow + i * 64;
            CPA16(dstbase + row * 80 + lcb,
                  (const char*)(G + (long long)row * ld) + lcb);
        }
    };

    auto load_stage = [&](int s, int buf) {
        const int k0 = s << 5;
        const uint32_t st = sb + buf * STAGE;
        load_tile(Ahz + (long long)m0 * lda + k0, lda, st);
        if (ASPL) load_tile(Alz + (long long)m0 * lda + k0, lda, st + OAL);
        load_tile(Bhz + (long long)n0 * ldb + k0, ldb, st + OB);
        if (BSPL) load_tile(Blz + (long long)n0 * ldb + k0, ldb, st + OBL);
    };

    float acc[2][8][4];
    #pragma unroll
    for (int i = 0; i < 2; i++)
        #pragma unroll
        for (int j = 0; j < 8; j++)
            #pragma unroll
            for (int c = 0; c < 4; c++) acc[i][j][c] = 0.f;

    // prologue: stages 0,1 in flight
    #pragma unroll
    for (int i = 0; i < 2; i++) {
        if (i < nst) load_stage(i, i);
        CPCOMMIT();
    }

    // ldmatrix lane coords
    const int arow = (l & 7) + ((l >> 3) & 1) * 8;
    const int akb0 = ((l >> 4) & 1) * 16;
    const int brow = (l & 7) + ((l >> 4) & 1) * 8;
    const int bkb0 = ((l >> 3) & 1) * 16;

    for (int s = 0; s < nst; s++) {
        CPWAIT1();                 // stage s complete (<=1 group pending)
        __syncthreads();           // all warps done reading buffer (s-1)%3
        if (s + 2 < nst) load_stage(s + 2, (s + 2) % 3);
        CPCOMMIT();                // real or empty: uniform group count

        const uint32_t st = sb + (s % 3) * STAGE;
        #pragma unroll
        for (int kt = 0; kt < 2; kt++) {
            uint32_t b[8][2];
            #pragma unroll
            for (int np = 0; np < 4; np++) {
                const int row = wn * 64 + np * 16 + brow;
                LDMX4(b[np*2][0], b[np*2][1], b[np*2+1][0], b[np*2+1][1],
                      st + OB + row * 80 + kt * 32 + bkb0);
            }
            uint32_t a[2][4];
            #pragma unroll
            for (int mt = 0; mt < 2; mt++) {
                const int row = wm * 32 + mt * 16 + arow;
                LDMX4(a[mt][0], a[mt][1], a[mt][2], a[mt][3],
                      st + row * 80 + kt * 32 + akb0);
            }
            #pragma unroll
            for (int mt = 0; mt < 2; mt++)
                #pragma unroll
                for (int nt = 0; nt < 8; nt++)
                    MMA16816(acc[mt][nt], a[mt], b[nt]);

            if (ASPL) {
                uint32_t a2[2][4];
                #pragma unroll
                for (int mt = 0; mt < 2; mt++) {
                    const int row = wm * 32 + mt * 16 + arow;
                    LDMX4(a2[mt][0], a2[mt][1], a2[mt][2], a2[mt][3],
                          st + OAL + row * 80 + kt * 32 + akb0);
                }
                #pragma unroll
                for (int mt = 0; mt < 2; mt++)
                    #pragma unroll
                    for (int nt = 0; nt < 8; nt++)
                        MMA16816(acc[mt][nt], a2[mt], b[nt]);
            }
            if (BSPL) {
                uint32_t b2[8][2];
                #pragma unroll
                for (int np = 0; np < 4; np++) {
                    const int row = wn * 64 + np * 16 + brow;
                    LDMX4(b2[np*2][0], b2[np*2][1], b2[np*2+1][0], b2[np*2+1][1],
                          st + OBL + row * 80 + kt * 32 + bkb0);
                }
                #pragma unroll
                for (int mt = 0; mt < 2; mt++)
                    #pragma unroll
                    for (int nt = 0; nt < 8; nt++)
                        MMA16816(acc[mt][nt], a[mt], b2[nt]);
            }
        }
    }

    // ----- epilogue -----
    #pragma unroll
    for (int mt = 0; mt < 2; mt++) {
        #pragma unroll
        for (int nt = 0; nt < 8; nt++) {
            const int row = m0 + wm * 32 + mt * 16 + (l >> 2);
            const int col = n0 + wn * 64 + nt * 8 + (l & 3) * 2;
            const float c0 = acc[mt][nt][0], c1 = acc[mt][nt][1];
            const float c2 = acc[mt][nt][2], c3 = acc[mt][nt][3];
            if (CHALF) {
                __half* Ch  = (__half*)Cv + (long long)blockIdx.z * sC;
                __half* Cll = Cl + (long long)blockIdx.z * sC;
                __half h0 = __float2half_rn(c0), h1 = __float2half_rn(c1);
                *(__half2*)(Ch  + (long long)row * ldc + col) = __halves2half2(h0, h1);
                *(__half2*)(Cll + (long long)row * ldc + col) =
                    __halves2half2(__float2half_rn(c0 - __half2float(h0)),
                                   __float2half_rn(c1 - __half2float(h1)));
                __half h2 = __float2half_rn(c2), h3 = __float2half_rn(c3);
                *(__half2*)(Ch  + (long long)(row + 8) * ldc + col) = __halves2half2(h2, h3);
                *(__half2*)(Cll + (long long)(row + 8) * ldc + col) =
                    __halves2half2(__float2half_rn(c2 - __half2float(h2)),
                                   __float2half_rn(c3 - __half2float(h3)));
            } else {
                float* Cf = (float*)Cv + (long long)blockIdx.z * sC;
                *(float2*)(Cf + (long long)row * ldc + col)       = make_float2(c0, c1);
                *(float2*)(Cf + (long long)(row + 8) * ldc + col) = make_float2(c2, c3);
            }
        }
    }
}

// ---------------------------------------------------------------------------
// fp32 -> split-fp16, float4 vectorized (n divisible by 1024)
// ---------------------------------------------------------------------------
__global__ void f2hsplit(const float* __restrict__ in, __half* __restrict__ oh,
                         __half* __restrict__ ol, int n)
{
    int i = (blockIdx.x * 256 + threadIdx.x) * 4;
    if (i >= n) return;
    float4 v = *(const float4*)(in + i);
    __half hx = __float2half_rn(v.x), hy = __float2half_rn(v.y);
    __half hz = __float2half_rn(v.z), hw = __float2half_rn(v.w);
    *(__half2*)(oh + i)     = __halves2half2(hx, hy);
    *(__half2*)(oh + i + 2) = __halves2half2(hz, hw);
    *(__half2*)(ol + i) = __halves2half2(
        __float2half_rn(v.x - __half2float(hx)), __float2half_rn(v.y - __half2float(hy)));
    *(__half2*)(ol + i + 2) = __halves2half2(
        __float2half_rn(v.z - __half2float(hz)), __float2half_rn(v.w - __half2float(hw)));
}

// fp32 -> fp16 (hi only), float4 vectorized
__global__ void f2h(const float* __restrict__ in, __half* __restrict__ oh, int n)
{
    int i = (blockIdx.x * 256 + threadIdx.x) * 4;
    if (i >= n) return;
    float4 v = *(const float4*)(in + i);
    *(__half2*)(oh + i)     = __halves2half2(__float2half_rn(v.x), __float2half_rn(v.y));
    *(__half2*)(oh + i + 2) = __halves2half2(__float2half_rn(v.z), __float2half_rn(v.w));
}

// ---------------------------------------------------------------------------
__global__ void rope_kernel(__half* Qh, __half* Ql, __half* Kh, __half* Kl,
                            const float* __restrict__ cosT, const float* __restrict__ sinT)
{
    int idx = blockIdx.x * blockDim.x + threadIdx.x;
    if (idx >= SEQ * NH * (ROPE / 2)) return;
    int i = idx & 31, h = (idx >> 5) & 15, s = idx >> 9;
    float c = cosT[s * 32 + i], sn = sinT[s * 32 + i];
    long long base = (long long)s * QKLD + h * HD + NOPE + 2 * i;
    float a, b, ra, rb; __half hh;
    a = __half2float(Qh[base])   + __half2float(Ql[base]);
    b = __half2float(Qh[base+1]) + __half2float(Ql[base+1]);
    ra = a * c - b * sn; rb = a * sn + b * c;
    hh = __float2half_rn(ra); Qh[base]   = hh; Ql[base]   = __float2half_rn(ra - __half2float(hh));
    hh = __float2half_rn(rb); Qh[base+1] = hh; Ql[base+1] = __float2half_rn(rb - __half2float(hh));
    a = __half2float(Kh[base])   + __half2float(Kl[base]);
    b = __half2float(Kh[base+1]) + __half2float(Kl[base+1]);
    ra = a * c - b * sn; rb = a * sn + b * c;
    hh = __float2half_rn(ra); Kh[base]   = hh; Kl[base]   = __float2half_rn(ra - __half2float(hh));
    hh = __float2half_rn(rb); Kh[base+1] = hh; Kl[base+1] = __float2half_rn(rb - __half2float(hh));
}

// ---------------------------------------------------------------------------
__global__ void transpose_h(const __half* __restrict__ in, __half* __restrict__ out)
{
    __shared__ __half t[32][33];
    int x = blockIdx.x * 32 + threadIdx.x;
    int y = blockIdx.y * 32 + threadIdx.y;
    #pragma unroll
    for (int j = 0; j < 32; j += 8)
        t[threadIdx.y + j][threadIdx.x] = in[(long long)(y + j) * DIM + x];
    __syncthreads();
    x = blockIdx.y * 32 + threadIdx.x;
    y = blockIdx.x * 32 + threadIdx.y;
    #pragma unroll
    for (int j = 0; j < 32; j += 8)
        out[(long long)(y + j) * SEQ + x] = t[threadIdx.x][threadIdx.y + j];
}

// ---------------------------------------------------------------------------
__global__ void softmax_causal(const float* __restrict__ S, __half* __restrict__ P, float scale)
{
    const int s = blockIdx.x, h = blockIdx.y;
    const float* row = S + ((long long)h * SEQ + s) * SEQ;
    __half* prow = P + ((long long)h * SEQ + s) * SEQ;
    const int n = s + 1;
    const int tid = threadIdx.x;
    __shared__ float buf[SEQ];
    __shared__ float red[8];

    float m = -1e30f;
    for (int t = tid; t < n; t += 256) { float v = row[t]; buf[t] = v; m = fmaxf(m, v); }
    #pragma unroll
    for (int o = 16; o; o >>= 1) m = fmaxf(m, __shfl_xor_sync(0xffffffffu, m, o));
    if ((tid & 31) == 0) red[tid >> 5] = m;
    __syncthreads();
    if (tid < 8) {
        float v = red[tid];
        #pragma unroll
        for (int o = 4; o; o >>= 1) v = fmaxf(v, __shfl_xor_sync(0xffu, v, o));
        if (tid == 0) red[0] = v;
    }
    __syncthreads();
    m = red[0];
    __syncthreads();

    float sum = 0.f;
    for (int t = tid; t < n; t += 256) {
        float e = __expf((buf[t] - m) * scale);
        buf[t] = e; sum += e;
    }
    #pragma unroll
    for (int o = 16; o; o >>= 1) sum += __shfl_xor_sync(0xffffffffu, sum, o);
    if ((tid & 31) == 0) red[tid >> 5] = sum;
    __syncthreads();
    if (tid < 8) {
        float v = red[tid];
        #pragma unroll
        for (int o = 4; o; o >>= 1) v += __shfl_xor_sync(0xffu, v, o);
        if (tid == 0) red[0] = v;
    }
    __syncthreads();
    const float inv = 1.f / red[0];
    __syncthreads();

    for (int t = tid * 2; t < SEQ; t += 512) {
        float a = (t     < n) ? buf[t]     * inv : 0.f;
        float b = (t + 1 < n) ? buf[t + 1] * inv : 0.f;
        *(__half2*)(prow + t) = __halves2half2(__float2half_rn(a), __float2half_rn(b));
    }
}

// ---------------------------------------------------------------------------
extern "C" void kernel_launch(void* const* d_in, const int* in_sizes, int n_in,
                              void* d_out, int out_size)
{
    const float* x  = (const float*)d_in[0];
    const float* wq = (const float*)d_in[1];
    const float* wk = (const float*)d_in[2];
    const float* wv = (const float*)d_in[3];
    const float* wo = (const float*)d_in[4];
    const float* fc = (const float*)d_in[5];
    const float* fs = (const float*)d_in[6];
    float* out = (float*)d_out;

    __half *xh, *xl, *wqh, *wkh, *wvh, *woh;
    __half *qh, *ql, *kh, *kl, *vh, *vl, *vth, *vtl, *p, *oh, *ol;
    float* sc;
    cudaGetSymbolAddress((void**)&xh, g_xh);   cudaGetSymbolAddress((void**)&xl, g_xl);
    cudaGetSymbolAddress((void**)&wqh, g_wqh);
    cudaGetSymbolAddress((void**)&wkh, g_wkh);
    cudaGetSymbolAddress((void**)&wvh, g_wvh);
    cudaGetSymbolAddress((void**)&woh, g_woh);
    cudaGetSymbolAddress((void**)&qh, g_qh);   cudaGetSymbolAddress((void**)&ql, g_ql);
    cudaGetSymbolAddress((void**)&kh, g_kh);   cudaGetSymbolAddress((void**)&kl, g_kl);
    cudaGetSymbolAddress((void**)&vh, g_vh);   cudaGetSymbolAddress((void**)&vl, g_vl);
    cudaGetSymbolAddress((void**)&vth, g_vth); cudaGetSymbolAddress((void**)&vtl, g_vtl);
    cudaGetSymbolAddress((void**)&p, g_p);
    cudaGetSymbolAddress((void**)&oh, g_oh);   cudaGetSymbolAddress((void**)&ol, g_ol);
    cudaGetSymbolAddress((void**)&sc, g_s);

    const int SMEM3 = 3 * 30720;  // 92160 (3-tile stages)
    cudaFuncSetAttribute((const void*)hgemm<1,0,0,0,1>, cudaFuncAttributeMaxDynamicSharedMemorySize, SMEM3);
    cudaFuncSetAttribute((const void*)hgemm<1,0,1,0,0>, cudaFuncAttributeMaxDynamicSharedMemorySize, SMEM3);
    cudaFuncSetAttribute((const void*)hgemm<0,1,0,1,1>, cudaFuncAttributeMaxDynamicSharedMemorySize, SMEM3);
    cudaFuncSetAttribute((const void*)hgemm<1,0,0,0,0>, cudaFuncAttributeMaxDynamicSharedMemorySize, SMEM3);

    // conversions: activations split, weights hi-only
    f2hsplit<<<SEQ * DIM / 1024, 256>>>(x, xh, xl, SEQ * DIM);
    f2h<<<QKLD * DIM / 1024, 256>>>(wq, wqh, QKLD * DIM);
    f2h<<<QKLD * DIM / 1024, 256>>>(wk, wkh, QKLD * DIM);
    f2h<<<DIM * DIM / 1024, 256>>>(wv, wvh, DIM * DIM);
    f2h<<<DIM * DIM / 1024, 256>>>(wo, woh, DIM * DIM);

    // projections: A = x (split), B = W (single fp16), split-fp16 out
    hgemm<1,0,0,0,1><<<dim3(QKLD / 128, SEQ / 128), 256, SMEM3>>>(
        xh, xl, wqh, nullptr, qh, ql, DIM, DIM, DIM, QKLD, 0, 0, 0);
    hgemm<1,0,0,0,1><<<dim3(QKLD / 128, SEQ / 128), 256, SMEM3>>>(
        xh, xl, wkh, nullptr, kh, kl, DIM, DIM, DIM, QKLD, 0, 0, 0);
    hgemm<1,0,0,0,1><<<dim3(DIM / 128, SEQ / 128), 256, SMEM3>>>(
        xh, xl, wvh, nullptr, vh, vl, DIM, DIM, DIM, DIM, 0, 0, 0);

    // RoPE
    rope_kernel<<<(SEQ * NH * 32 + 255) / 256, 256>>>(qh, ql, kh, kl, fc, fs);

    // V transpose -> [DIM][SEQ] K-major for PV
    transpose_h<<<dim3(64, 64), dim3(32, 8)>>>(vh, vth);
    transpose_h<<<dim3(64, 64), dim3(32, 8)>>>(vl, vtl);

    // scores (causal block skip): A = q (split), B = k hi, fp32 out
    hgemm<1,0,1,0,0><<<dim3(SEQ / 128, SEQ / 128, NH), 256, SMEM3>>>(
        qh, ql, kh, nullptr, sc, nullptr, HD, QKLD, QKLD, SEQ,
        HD, HD, (long long)SEQ * SEQ);

    // softmax -> fp16 probs
    softmax_causal<<<dim3(SEQ, NH), 256>>>(sc, p, rsqrtf((float)HD));

    // PV (causal K-limit): A = probs (single), B = V (split)
    hgemm<0,1,0,1,1><<<dim3(1, SEQ / 128, NH), 256, SMEM3>>>(
        p, nullptr, vth, vtl, oh, ol, SEQ, SEQ, SEQ, DIM,
        (long long)SEQ * SEQ, (long long)VD * SEQ, VD);

    // output projection: A = o (split), B = wo hi, fp32 out
    hgemm<1,0,0,0,0><<<dim3(DIM / 128, SEQ / 128), 256, SMEM3>>>(
        oh, ol, woh, nullptr, out, nullptr, DIM, DIM, DIM, DIM, 0, 0, 0);
}